// round 10
// baseline (speedup 1.0000x reference)
#include <cuda_runtime.h>
#include <cstdint>
#include <math.h>

// ---------------------------------------------------------------------------
// 2-layer LSTM (B=64, T=2048, D=64, H=512) + linear head + log_softmax.
//
// Persistent weight-stationary kernel; round r = layer0 step r + layer1 step
// r-1; one global barrier per round (2049 rounds).
//
// R10 = R6 parallelism (512 threads, 16 warps = 16 k-slices, two-stage slice
// reduce) x R9 inner loop (lane-halves own gate-row pairs 0-3/4-7, each lane
// owns 4 batches via LDG.128; per k two bank-disjoint broadcast LDS.128 feed
// 16 fma.rn.f32x2). Layers sequential (16 u64 accs) to stay under the
// 128-reg cap at 512 threads. FMA floor 12.8K cyc/round/SMSP now binds.
// ---------------------------------------------------------------------------

namespace {
constexpr int B_   = 64;
constexpr int T_   = 2048;
constexpr int D_   = 64;
constexpr int H_   = 512;
constexpr int OUT_ = 10;
constexpr int NCTA = 128;
constexpr int NTHR = 512;                 // 16 warps = 16 k-slices
constexpr int ROWS = 16;                  // gate rows per layer per CTA
constexpr int K0   = H_ + D_;
constexpr int K1   = H_ + H_;

constexpr size_t OFF_W0  = 0;                                   // [576][16]
constexpr size_t OFF_W1  = OFF_W0 + (size_t)K0 * ROWS * 4;      //  36864
constexpr size_t OFF_GP0 = OFF_W1 + (size_t)K1 * ROWS * 4;      // 102400
constexpr size_t OFF_GP1 = OFF_GP0 + (size_t)8 * 8 * B_ * 8;    // 135168
constexpr size_t OFF_CST = OFF_GP1 + (size_t)8 * 8 * B_ * 8;    // 167936
constexpr size_t OFF_BIA = OFF_CST + 2048;                      // 169984
constexpr size_t SMEM_BYTES = OFF_BIA + 128;                    // 170112

constexpr int HV_STRIDE = 521;                  // head staging
constexpr size_t OFF_LG = (size_t)B_ * HV_STRIDE * 4;           // 133376
}

// Static device scratch (no runtime allocation).
__device__ float g_h1[(size_t)T_ * H_ * B_];   // layer0 h, [t][unit][b]
__device__ float g_h2[(size_t)T_ * H_ * B_];   // layer1 h, [t][unit][b]
__device__ float g_xT[(size_t)T_ * D_ * B_];   // x transposed, [t][k][b]
__device__ int   g_cnt[T_ + 1];                // per-round arrival counters

__device__ __forceinline__ void ffma2(uint64_t& acc, uint64_t a, uint64_t b) {
    asm("fma.rn.f32x2 %0, %1, %2, %0;" : "+l"(acc) : "l"(a), "l"(b));
}
__device__ __forceinline__ void addf2(uint64_t& acc, uint64_t a) {
    asm("add.rn.f32x2 %0, %0, %1;" : "+l"(acc) : "l"(a));
}
__device__ __forceinline__ uint64_t dup2(float x) {
    uint64_t r;
    asm("mov.b64 %0, {%1, %1};" : "=l"(r) : "f"(x));
    return r;
}
__device__ __forceinline__ float2 unpk(uint64_t v) {
    float2 f;
    asm("mov.b64 {%0, %1}, %2;" : "=f"(f.x), "=f"(f.y) : "l"(v));
    return f;
}
__device__ __forceinline__ int ld_acq(const int* p) {
    int v;
    asm volatile("ld.global.acquire.gpu.b32 %0, [%1];" : "=r"(v) : "l"(p));
    return v;
}
__device__ __forceinline__ float fast_sigmoid(float x) {
    return 1.f / (1.f + __expf(-x));
}
__device__ __forceinline__ float fast_tanh(float x) {
    float a = fabsf(x);
    float t = __expf(-2.f * a);
    float r = (1.f - t) / (1.f + t);
    return copysignf(r, x);
}

// a[p*4+j] += Wpair[ph+p][k] * in[k][b4+j]; lane covers pairs ph..ph+3
// (pq = ph/2 = ulonglong2 index) and batches b4..b4+3.
__device__ __forceinline__ void gemv4(uint64_t a[16],
                                      const float* __restrict__ wsm,
                                      const float* __restrict__ in,
                                      int kb, int ke, int b4, int pq) {
#pragma unroll 4
    for (int k = kb; k < ke; ++k) {
        float4 v = *(const float4*)(in + (size_t)k * B_ + b4);
        uint64_t x0 = dup2(v.x), x1 = dup2(v.y);
        uint64_t x2 = dup2(v.z), x3 = dup2(v.w);
        const ulonglong2* wv = (const ulonglong2*)(wsm + (size_t)k * ROWS);
        ulonglong2 wA = wv[pq];
        ulonglong2 wB = wv[pq + 1];
        ffma2(a[0],  wA.x, x0); ffma2(a[1],  wA.x, x1);
        ffma2(a[2],  wA.x, x2); ffma2(a[3],  wA.x, x3);
        ffma2(a[4],  wA.y, x0); ffma2(a[5],  wA.y, x1);
        ffma2(a[6],  wA.y, x2); ffma2(a[7],  wA.y, x3);
        ffma2(a[8],  wB.x, x0); ffma2(a[9],  wB.x, x1);
        ffma2(a[10], wB.x, x2); ffma2(a[11], wB.x, x3);
        ffma2(a[12], wB.y, x0); ffma2(a[13], wB.y, x1);
        ffma2(a[14], wB.y, x2); ffma2(a[15], wB.y, x3);
    }
}

// prep: zero counters + transpose x[b][t][k] -> g_xT[t][k][b]
__global__ void prep_kernel(const float* __restrict__ x) {
    __shared__ float tile[64][65];
    int t = blockIdx.x;
    if (threadIdx.x == 0) {
        g_cnt[t] = 0;
        if (t == 0) g_cnt[T_] = 0;
    }
    for (int i = threadIdx.x; i < 64 * 64; i += blockDim.x) {
        int b = i >> 6, k = i & 63;
        tile[b][k] = x[(size_t)b * T_ * D_ + (size_t)t * D_ + k];
    }
    __syncthreads();
    for (int i = threadIdx.x; i < 64 * 64; i += blockDim.x) {
        int k = i >> 6, b = i & 63;
        g_xT[(size_t)t * D_ * B_ + (size_t)k * B_ + b] = tile[b][k];
    }
}

__global__ __launch_bounds__(NTHR, 1)
void lstm_kernel(const float* __restrict__ Wih0, const float* __restrict__ Whh0,
                 const float* __restrict__ bih0, const float* __restrict__ bhh0,
                 const float* __restrict__ Wih1, const float* __restrict__ Whh1,
                 const float* __restrict__ bih1, const float* __restrict__ bhh1,
                 const float* __restrict__ Wlin, const float* __restrict__ blin,
                 float* __restrict__ out) {
    extern __shared__ unsigned char smem[];
    float*    w0   = (float*)(smem + OFF_W0);      // [K0][16]
    float*    w1   = (float*)(smem + OFF_W1);      // [K1][16]
    uint64_t* gp0  = (uint64_t*)(smem + OFF_GP0);  // [8 slice][8 pair][64 b]
    uint64_t* gp1  = (uint64_t*)(smem + OFF_GP1);  // [8 slice][8 pair][64 b]
    float*    cst  = (float*)(smem + OFF_CST);     // [2][4][64]
    float*    bias = (float*)(smem + OFF_BIA);     // [2][16]

    const int tid    = threadIdx.x;
    const int lane   = tid & 31;
    const int s      = tid >> 5;                   // k-slice 0..15
    const int lane16 = lane & 15;
    const int ph     = (lane >> 4) << 2;           // pair base: 0 or 4
    const int pq     = ph >> 1;                    // ulonglong2 index: 0 or 2
    const int b4     = 4 * lane16;                 // batches b4..b4+3
    const int j0     = blockIdx.x * 4;
    const bool hi    = (s >= 8);
    const int  slo   = s & 7;

    // ---- load weights (row r = gate*4 + j; k<H_ -> W_hh else W_ih) ----
    for (int idx = tid; idx < K0 * ROWS; idx += NTHR) {
        int k = idx >> 4, r = idx & 15;
        int row = (r >> 2) * H_ + j0 + (r & 3);
        w0[idx] = (k < H_) ? Whh0[(size_t)row * H_ + k]
                           : Wih0[(size_t)row * D_ + (k - H_)];
    }
    for (int idx = tid; idx < K1 * ROWS; idx += NTHR) {
        int k = idx >> 4, r = idx & 15;
        int row = (r >> 2) * H_ + j0 + (r & 3);
        w1[idx] = (k < H_) ? Whh1[(size_t)row * H_ + k]
                           : Wih1[(size_t)row * H_ + (k - H_)];
    }
    if (tid < 32) {
        int l = tid >> 4, r = tid & 15;
        int row = (r >> 2) * H_ + j0 + (r & 3);
        bias[tid] = l ? (bih1[row] + bhh1[row]) : (bih0[row] + bhh0[row]);
    }
    cst[tid] = 0.f;                                // exactly 512 entries
    __syncthreads();

    const float* w0x  = w0 + (size_t)H_ * ROWS;    // layer0 x-ff rows
    const float* w1ff = w1 + (size_t)H_ * ROWS;    // layer1 h1-ff rows

    for (int r = 0; r <= T_; ++r) {
        uint64_t a[16];

        // ================= layer 0 GEMV (step r) =================
#pragma unroll
        for (int i = 0; i < 16; ++i) a[i] = 0ull;
        if (r < T_) {
            if (r >= 1)
                gemv4(a, w0, g_h1 + (size_t)(r - 1) * H_ * B_,
                      s * 32, s * 32 + 32, b4, pq);
            gemv4(a, w0x, g_xT + (size_t)r * D_ * B_,
                  s * 4, s * 4 + 4, b4, pq);
        }
        if (hi) {
#pragma unroll
            for (int p = 0; p < 4; ++p) {
                uint64_t* base = gp0 + (size_t)(slo * 8 + ph + p) * B_ + b4;
                *(ulonglong2*)base       = make_ulonglong2(a[p*4+0], a[p*4+1]);
                *(ulonglong2*)(base + 2) = make_ulonglong2(a[p*4+2], a[p*4+3]);
            }
        }
        __syncthreads();
        if (!hi) {
#pragma unroll
            for (int p = 0; p < 4; ++p) {
                uint64_t* base = gp0 + (size_t)(slo * 8 + ph + p) * B_ + b4;
                ulonglong2 o1 = *(ulonglong2*)base;
                ulonglong2 o2 = *(ulonglong2*)(base + 2);
                addf2(a[p*4+0], o1.x); addf2(a[p*4+1], o1.y);
                addf2(a[p*4+2], o2.x); addf2(a[p*4+3], o2.y);
                *(ulonglong2*)base       = make_ulonglong2(a[p*4+0], a[p*4+1]);
                *(ulonglong2*)(base + 2) = make_ulonglong2(a[p*4+2], a[p*4+3]);
            }
        }

        // ================= layer 1 GEMV (step r-1) =================
#pragma unroll
        for (int i = 0; i < 16; ++i) a[i] = 0ull;
        if (r >= 1) {
            gemv4(a, w1ff, g_h1 + (size_t)(r - 1) * H_ * B_,
                  s * 32, s * 32 + 32, b4, pq);
            if (r >= 2)
                gemv4(a, w1, g_h2 + (size_t)(r - 2) * H_ * B_,
                      s * 32, s * 32 + 32, b4, pq);
        }
        if (hi) {
#pragma unroll
            for (int p = 0; p < 4; ++p) {
                uint64_t* base = gp1 + (size_t)(slo * 8 + ph + p) * B_ + b4;
                *(ulonglong2*)base       = make_ulonglong2(a[p*4+0], a[p*4+1]);
                *(ulonglong2*)(base + 2) = make_ulonglong2(a[p*4+2], a[p*4+3]);
            }
        }
        __syncthreads();
        if (!hi) {
#pragma unroll
            for (int p = 0; p < 4; ++p) {
                uint64_t* base = gp1 + (size_t)(slo * 8 + ph + p) * B_ + b4;
                ulonglong2 o1 = *(ulonglong2*)base;
                ulonglong2 o2 = *(ulonglong2*)(base + 2);
                addf2(a[p*4+0], o1.x); addf2(a[p*4+1], o1.y);
                addf2(a[p*4+2], o2.x); addf2(a[p*4+3], o2.y);
                *(ulonglong2*)base       = make_ulonglong2(a[p*4+0], a[p*4+1]);
                *(ulonglong2*)(base + 2) = make_ulonglong2(a[p*4+2], a[p*4+3]);
            }
        }
        __syncthreads();

        // ---- gates + state update: tid -> (layer l, pair p, batch b) ----
        if (tid < 256) {
            int l = tid >> 7, p = (tid >> 6) & 1, b = tid & 63;
            bool act = l ? (r >= 1) : (r < T_);
            if (act) {
                const uint64_t* gpl = l ? gp1 : gp0;
                uint64_t sg[4];
#pragma unroll
                for (int g = 0; g < 4; ++g) {
                    int pi = g * 2 + p;
                    uint64_t v = gpl[(size_t)pi * B_ + b];
#pragma unroll
                    for (int ss = 1; ss < 8; ++ss)
                        addf2(v, gpl[((size_t)ss * 8 + pi) * B_ + b]);
                    sg[g] = v;
                }
                float2 vi = unpk(sg[0]), vf = unpk(sg[1]);
                float2 vg = unpk(sg[2]), vo = unpk(sg[3]);
                const float* bb = bias + l * 16;
                int t = l ? (r - 1) : r;
                float* hout = l ? g_h2 : g_h1;
#pragma unroll
                for (int j2 = 0; j2 < 2; ++j2) {
                    int j = 2 * p + j2;
                    float gi = (j2 ? vi.y : vi.x) + bb[j];
                    float gf = (j2 ? vf.y : vf.x) + bb[4 + j];
                    float gg = (j2 ? vg.y : vg.x) + bb[8 + j];
                    float go = (j2 ? vo.y : vo.x) + bb[12 + j];
                    float si = fast_sigmoid(gi);
                    float sf = fast_sigmoid(gf);
                    float so = fast_sigmoid(go);
                    float tg = fast_tanh(gg);
                    int ci = (l * 4 + j) * 64 + b;
                    float c = sf * cst[ci] + si * tg;
                    cst[ci] = c;
                    hout[(size_t)t * H_ * B_ + (size_t)(j0 + j) * B_ + b]
                        = so * fast_tanh(c);
                }
            }
        }
        __syncthreads();

        // ---- global barrier for round r ----
        if (tid == 0) {
            __threadfence();
            atomicAdd(&g_cnt[r], 1);
            while (ld_acq(&g_cnt[r]) < NCTA) {}
        }
        __syncthreads();
    }

    // ---- head on CTA 0: logits = h2[:,T-1] @ Wlin^T + blin; log_softmax ----
    if (blockIdx.x == 0) {
        float* hv = (float*)smem;                      // [64][521]
        float* lg = (float*)(smem + OFF_LG);           // [640]
        const float* h2l = g_h2 + (size_t)(T_ - 1) * H_ * B_;
        for (int idx = tid; idx < H_ * B_; idx += NTHR) {
            int k = idx >> 6, b = idx & 63;
            hv[b * HV_STRIDE + k] = h2l[idx];
        }
        __syncthreads();
        for (int pr = s * 40; pr < s * 40 + 40; ++pr) {
            int b = pr / OUT_, o = pr % OUT_;
            float sum = 0.f;
            for (int i = lane; i < H_; i += 32)
                sum += hv[b * HV_STRIDE + i] * Wlin[(size_t)o * H_ + i];
#pragma unroll
            for (int off = 16; off; off >>= 1)
                sum += __shfl_xor_sync(0xffffffffu, sum, off);
            if (lane == 0) lg[pr] = sum + blin[o];
        }
        __syncthreads();
        if (tid < B_) {
            float m = -1e30f;
#pragma unroll
            for (int q = 0; q < OUT_; ++q) m = fmaxf(m, lg[tid * OUT_ + q]);
            float z = 0.f;
#pragma unroll
            for (int q = 0; q < OUT_; ++q) z += expf(lg[tid * OUT_ + q] - m);
            float lse = m + logf(z);
#pragma unroll
            for (int q = 0; q < OUT_; ++q)
                out[tid * OUT_ + q] = lg[tid * OUT_ + q] - lse;
        }
    }
}

extern "C" void kernel_launch(void* const* d_in, const int* in_sizes, int n_in,
                              void* d_out, int out_size) {
    const float* x    = (const float*)d_in[0];
    const float* Wih0 = (const float*)d_in[1];
    const float* Whh0 = (const float*)d_in[2];
    const float* bih0 = (const float*)d_in[3];
    const float* bhh0 = (const float*)d_in[4];
    const float* Wih1 = (const float*)d_in[5];
    const float* Whh1 = (const float*)d_in[6];
    const float* bih1 = (const float*)d_in[7];
    const float* bhh1 = (const float*)d_in[8];
    const float* Wlin = (const float*)d_in[9];
    const float* blin = (const float*)d_in[10];
    float* out = (float*)d_out;

    cudaFuncSetAttribute(lstm_kernel,
                         cudaFuncAttributeMaxDynamicSharedMemorySize,
                         (int)SMEM_BYTES);

    prep_kernel<<<T_, 256>>>(x);
    lstm_kernel<<<NCTA, NTHR, SMEM_BYTES>>>(Wih0, Whh0, bih0, bhh0,
                                            Wih1, Whh1, bih1, bhh1,
                                            Wlin, blin, out);
}

// round 11
// speedup vs baseline: 1.5855x; 1.5855x over previous
#include <cuda_runtime.h>
#include <cstdint>
#include <math.h>

// ---------------------------------------------------------------------------
// 2-layer LSTM (B=64, T=2048, D=64, H=512) + linear head + log_softmax.
//
// Persistent weight-stationary kernel; round r = layer0 step r + layer1 step
// r-1; one global barrier per round (2049 rounds). Base = R6 champion.
//
// R11 change (only): k-parity lane split in the GEMV. Warp = (k-slice 0..7,
// batch-half). Lane-half h processes k+h; lane owns 2 batches. Per k-pair:
// one coalesced LDG.64 (half-warps load different rows - zero duplication)
// + 4 LDS.128 serving both halves' weight rows (64B apart, distinct bank
// quads) -> gemv L1 wavefronts HALVED vs champion. Halves combined via
// shfl_xor(16), then champion's contiguous store from lanes 0-15 only; the
// hi/lo RMW reduce stage is deleted (5 -> 3 syncs/round).
// ---------------------------------------------------------------------------

namespace {
constexpr int B_   = 64;
constexpr int T_   = 2048;
constexpr int D_   = 64;
constexpr int H_   = 512;
constexpr int OUT_ = 10;
constexpr int NCTA = 128;
constexpr int NTHR = 512;                 // 16 warps = 8 k-slices x 2 b-halves
constexpr int ROWS = 16;                  // gate rows per layer per CTA
constexpr int K0   = H_ + D_;
constexpr int K1   = H_ + H_;

constexpr size_t OFF_W0  = 0;                                   // [576][16]
constexpr size_t OFF_W1  = OFF_W0 + (size_t)K0 * ROWS * 4;      //  36864
constexpr size_t OFF_GP0 = OFF_W1 + (size_t)K1 * ROWS * 4;      // 102400
constexpr size_t OFF_GP1 = OFF_GP0 + (size_t)8 * 8 * B_ * 8;    // 135168
constexpr size_t OFF_CST = OFF_GP1 + (size_t)8 * 8 * B_ * 8;    // 167936
constexpr size_t OFF_BIA = OFF_CST + 2048;                      // 169984
constexpr size_t SMEM_BYTES = OFF_BIA + 128;                    // 170112

constexpr int HV_STRIDE = 521;                  // head staging
constexpr size_t OFF_LG = (size_t)B_ * HV_STRIDE * 4;           // 133376
}

// Static device scratch (no runtime allocation).
__device__ float g_h1[(size_t)T_ * H_ * B_];   // layer0 h, [t][unit][b]
__device__ float g_h2[(size_t)T_ * H_ * B_];   // layer1 h, [t][unit][b]
__device__ float g_xT[(size_t)T_ * D_ * B_];   // x transposed, [t][k][b]
__device__ int   g_cnt[T_ + 1];                // per-round arrival counters

__device__ __forceinline__ void ffma2(uint64_t& acc, uint64_t a, uint64_t b) {
    asm("fma.rn.f32x2 %0, %1, %2, %0;" : "+l"(acc) : "l"(a), "l"(b));
}
__device__ __forceinline__ void addf2(uint64_t& acc, uint64_t a) {
    asm("add.rn.f32x2 %0, %0, %1;" : "+l"(acc) : "l"(a));
}
__device__ __forceinline__ uint64_t dup2(float x) {
    uint64_t r;
    asm("mov.b64 %0, {%1, %1};" : "=l"(r) : "f"(x));
    return r;
}
__device__ __forceinline__ float2 unpk(uint64_t v) {
    float2 f;
    asm("mov.b64 {%0, %1}, %2;" : "=f"(f.x), "=f"(f.y) : "l"(v));
    return f;
}
__device__ __forceinline__ int ld_acq(const int* p) {
    int v;
    asm volatile("ld.global.acquire.gpu.b32 %0, [%1];" : "=r"(v) : "l"(p));
    return v;
}
__device__ __forceinline__ float fast_sigmoid(float x) {
    return 1.f / (1.f + __expf(-x));
}
__device__ __forceinline__ float fast_tanh(float x) {
    float a = fabsf(x);
    float t = __expf(-2.f * a);
    float r = (1.f - t) / (1.f + t);
    return copysignf(r, x);
}

// k-parity GEMV: this lane processes rows kk = kb+h, kb+2+h, ... (its own
// parity) for its 2 batches (b2, b2+1). aA[p]/aB[p] = row-pair p sums.
// Per k-pair: 1 coalesced LDG.64 + 4 LDS.128 shared across both halves.
__device__ __forceinline__ void gemv2k(uint64_t aA[8], uint64_t aB[8],
                                       const float* __restrict__ wsm,
                                       const float* __restrict__ in,
                                       int kb, int ke, int b2, int h) {
#pragma unroll 8
    for (int k = kb; k < ke; k += 2) {
        int kk = k + h;
        float2 v = *(const float2*)(in + (size_t)kk * B_ + b2);
        uint64_t x0 = dup2(v.x);
        uint64_t x1 = dup2(v.y);
        const ulonglong2* wv = (const ulonglong2*)(wsm + (size_t)kk * ROWS);
#pragma unroll
        for (int q = 0; q < 4; ++q) {
            ulonglong2 wp = wv[q];
            ffma2(aA[2 * q],     wp.x, x0);
            ffma2(aA[2 * q + 1], wp.y, x0);
            ffma2(aB[2 * q],     wp.x, x1);
            ffma2(aB[2 * q + 1], wp.y, x1);
        }
    }
}

// Combine the two k-parity halves and store (lanes 0-15 only, contiguous).
__device__ __forceinline__ void combine_store(uint64_t aA[8], uint64_t aB[8],
                                              uint64_t* __restrict__ gp,
                                              int ks, int b2, int lane) {
#pragma unroll
    for (int p = 0; p < 8; ++p) {
        unsigned long long oA = __shfl_xor_sync(0xffffffffu,
                                                (unsigned long long)aA[p], 16);
        unsigned long long oB = __shfl_xor_sync(0xffffffffu,
                                                (unsigned long long)aB[p], 16);
        addf2(aA[p], (uint64_t)oA);
        addf2(aB[p], (uint64_t)oB);
    }
    if (lane < 16) {
#pragma unroll
        for (int p = 0; p < 8; ++p) {
            *(ulonglong2*)(gp + (size_t)(ks * 8 + p) * B_ + b2)
                = make_ulonglong2(aA[p], aB[p]);
        }
    }
}

// prep: zero counters + transpose x[b][t][k] -> g_xT[t][k][b]
__global__ void prep_kernel(const float* __restrict__ x) {
    __shared__ float tile[64][65];
    int t = blockIdx.x;
    if (threadIdx.x == 0) {
        g_cnt[t] = 0;
        if (t == 0) g_cnt[T_] = 0;
    }
    for (int i = threadIdx.x; i < 64 * 64; i += blockDim.x) {
        int b = i >> 6, k = i & 63;
        tile[b][k] = x[(size_t)b * T_ * D_ + (size_t)t * D_ + k];
    }
    __syncthreads();
    for (int i = threadIdx.x; i < 64 * 64; i += blockDim.x) {
        int k = i >> 6, b = i & 63;
        g_xT[(size_t)t * D_ * B_ + (size_t)k * B_ + b] = tile[b][k];
    }
}

__global__ __launch_bounds__(NTHR, 1)
void lstm_kernel(const float* __restrict__ Wih0, const float* __restrict__ Whh0,
                 const float* __restrict__ bih0, const float* __restrict__ bhh0,
                 const float* __restrict__ Wih1, const float* __restrict__ Whh1,
                 const float* __restrict__ bih1, const float* __restrict__ bhh1,
                 const float* __restrict__ Wlin, const float* __restrict__ blin,
                 float* __restrict__ out) {
    extern __shared__ unsigned char smem[];
    float*    w0   = (float*)(smem + OFF_W0);      // [K0][16]
    float*    w1   = (float*)(smem + OFF_W1);      // [K1][16]
    uint64_t* gp0  = (uint64_t*)(smem + OFF_GP0);  // [8 slice][8 pair][64 b]
    uint64_t* gp1  = (uint64_t*)(smem + OFF_GP1);  // [8 slice][8 pair][64 b]
    float*    cst  = (float*)(smem + OFF_CST);     // [2][4][64]
    float*    bias = (float*)(smem + OFF_BIA);     // [2][16]

    const int tid  = threadIdx.x;
    const int lane = tid & 31;
    const int s    = tid >> 5;                     // warp 0..15
    const int ks   = s & 7;                        // k-slice 0..7
    const int bh   = s >> 3;                       // batch half 0..1
    const int h    = lane >> 4;                    // k-parity 0..1
    const int m    = lane & 15;
    const int b2   = bh * 32 + 2 * m;              // batches b2, b2+1
    const int j0   = blockIdx.x * 4;

    // ---- load weights (row r = gate*4 + j; k<H_ -> W_hh else W_ih) ----
    for (int idx = tid; idx < K0 * ROWS; idx += NTHR) {
        int k = idx >> 4, r = idx & 15;
        int row = (r >> 2) * H_ + j0 + (r & 3);
        w0[idx] = (k < H_) ? Whh0[(size_t)row * H_ + k]
                           : Wih0[(size_t)row * D_ + (k - H_)];
    }
    for (int idx = tid; idx < K1 * ROWS; idx += NTHR) {
        int k = idx >> 4, r = idx & 15;
        int row = (r >> 2) * H_ + j0 + (r & 3);
        w1[idx] = (k < H_) ? Whh1[(size_t)row * H_ + k]
                           : Wih1[(size_t)row * H_ + (k - H_)];
    }
    if (tid < 32) {
        int l = tid >> 4, r = tid & 15;
        int row = (r >> 2) * H_ + j0 + (r & 3);
        bias[tid] = l ? (bih1[row] + bhh1[row]) : (bih0[row] + bhh0[row]);
    }
    cst[tid] = 0.f;                                // exactly 512 entries
    __syncthreads();

    const float* w0x  = w0 + (size_t)H_ * ROWS;    // layer0 x-ff rows
    const float* w1ff = w1 + (size_t)H_ * ROWS;    // layer1 h1-ff rows

    for (int r = 0; r <= T_; ++r) {
        uint64_t aA[8], aB[8];

        // ================= layer 0 GEMV (step r) =================
#pragma unroll
        for (int i = 0; i < 8; ++i) { aA[i] = 0ull; aB[i] = 0ull; }
        if (r < T_) {
            if (r >= 1)
                gemv2k(aA, aB, w0, g_h1 + (size_t)(r - 1) * H_ * B_,
                       ks * 64, ks * 64 + 64, b2, h);
            gemv2k(aA, aB, w0x, g_xT + (size_t)r * D_ * B_,
                   ks * 8, ks * 8 + 8, b2, h);
        }
        combine_store(aA, aB, gp0, ks, b2, lane);

        // ================= layer 1 GEMV (step r-1) =================
#pragma unroll
        for (int i = 0; i < 8; ++i) { aA[i] = 0ull; aB[i] = 0ull; }
        if (r >= 1) {
            gemv2k(aA, aB, w1ff, g_h1 + (size_t)(r - 1) * H_ * B_,
                   ks * 64, ks * 64 + 64, b2, h);
            if (r >= 2)
                gemv2k(aA, aB, w1, g_h2 + (size_t)(r - 2) * H_ * B_,
                       ks * 64, ks * 64 + 64, b2, h);
        }
        combine_store(aA, aB, gp1, ks, b2, lane);
        __syncthreads();

        // ---- gates + state update: tid -> (layer l, pair p, batch b) ----
        if (tid < 256) {
            int l = tid >> 7, p = (tid >> 6) & 1, b = tid & 63;
            bool act = l ? (r >= 1) : (r < T_);
            if (act) {
                const uint64_t* gpl = l ? gp1 : gp0;
                uint64_t sg[4];
#pragma unroll
                for (int g = 0; g < 4; ++g) {
                    int pi = g * 2 + p;
                    uint64_t v = gpl[(size_t)pi * B_ + b];
#pragma unroll
                    for (int ss = 1; ss < 8; ++ss)
                        addf2(v, gpl[((size_t)ss * 8 + pi) * B_ + b]);
                    sg[g] = v;
                }
                float2 vi = unpk(sg[0]), vf = unpk(sg[1]);
                float2 vg = unpk(sg[2]), vo = unpk(sg[3]);
                const float* bb = bias + l * 16;
                int t = l ? (r - 1) : r;
                float* hout = l ? g_h2 : g_h1;
#pragma unroll
                for (int j2 = 0; j2 < 2; ++j2) {
                    int j = 2 * p + j2;
                    float gi = (j2 ? vi.y : vi.x) + bb[j];
                    float gf = (j2 ? vf.y : vf.x) + bb[4 + j];
                    float gg = (j2 ? vg.y : vg.x) + bb[8 + j];
                    float go = (j2 ? vo.y : vo.x) + bb[12 + j];
                    float si = fast_sigmoid(gi);
                    float sf = fast_sigmoid(gf);
                    float so = fast_sigmoid(go);
                    float tg = fast_tanh(gg);
                    int ci = (l * 4 + j) * 64 + b;
                    float c = sf * cst[ci] + si * tg;
                    cst[ci] = c;
                    hout[(size_t)t * H_ * B_ + (size_t)(j0 + j) * B_ + b]
                        = so * fast_tanh(c);
                }
            }
        }
        __syncthreads();

        // ---- global barrier for round r ----
        if (tid == 0) {
            __threadfence();
            atomicAdd(&g_cnt[r], 1);
            while (ld_acq(&g_cnt[r]) < NCTA) {}
        }
        __syncthreads();
    }

    // ---- head on CTA 0: logits = h2[:,T-1] @ Wlin^T + blin; log_softmax ----
    if (blockIdx.x == 0) {
        float* hv = (float*)smem;                      // [64][521]
        float* lg = (float*)(smem + OFF_LG);           // [640]
        const float* h2l = g_h2 + (size_t)(T_ - 1) * H_ * B_;
        for (int idx = tid; idx < H_ * B_; idx += NTHR) {
            int k = idx >> 6, b = idx & 63;
            hv[b * HV_STRIDE + k] = h2l[idx];
        }
        __syncthreads();
        for (int pr = s * 40; pr < s * 40 + 40; ++pr) {
            int b = pr / OUT_, o = pr % OUT_;
            float sum = 0.f;
            for (int i = lane; i < H_; i += 32)
                sum += hv[b * HV_STRIDE + i] * Wlin[(size_t)o * H_ + i];
#pragma unroll
            for (int off = 16; off; off >>= 1)
                sum += __shfl_xor_sync(0xffffffffu, sum, off);
            if (lane == 0) lg[pr] = sum + blin[o];
        }
        __syncthreads();
        if (tid < B_) {
            float mx = -1e30f;
#pragma unroll
            for (int q = 0; q < OUT_; ++q) mx = fmaxf(mx, lg[tid * OUT_ + q]);
            float z = 0.f;
#pragma unroll
            for (int q = 0; q < OUT_; ++q) z += expf(lg[tid * OUT_ + q] - mx);
            float lse = mx + logf(z);
#pragma unroll
            for (int q = 0; q < OUT_; ++q)
                out[tid * OUT_ + q] = lg[tid * OUT_ + q] - lse;
        }
    }
}

extern "C" void kernel_launch(void* const* d_in, const int* in_sizes, int n_in,
                              void* d_out, int out_size) {
    const float* x    = (const float*)d_in[0];
    const float* Wih0 = (const float*)d_in[1];
    const float* Whh0 = (const float*)d_in[2];
    const float* bih0 = (const float*)d_in[3];
    const float* bhh0 = (const float*)d_in[4];
    const float* Wih1 = (const float*)d_in[5];
    const float* Whh1 = (const float*)d_in[6];
    const float* bih1 = (const float*)d_in[7];
    const float* bhh1 = (const float*)d_in[8];
    const float* Wlin = (const float*)d_in[9];
    const float* blin = (const float*)d_in[10];
    float* out = (float*)d_out;

    cudaFuncSetAttribute(lstm_kernel,
                         cudaFuncAttributeMaxDynamicSharedMemorySize,
                         (int)SMEM_BYTES);

    prep_kernel<<<T_, 256>>>(x);
    lstm_kernel<<<NCTA, NTHR, SMEM_BYTES>>>(Wih0, Whh0, bih0, bhh0,
                                            Wih1, Whh1, bih1, bhh1,
                                            Wlin, blin, out);
}